// round 12
// baseline (speedup 1.0000x reference)
#include <cuda_runtime.h>
#include <cstdint>
#include <math.h>

// Problem constants
#define BB 4
#define SS 1024
#define CC 1280
#define HH 20
#define DD 64
#define ATT_SCALE 0.125f              // 64^-0.5
#define SC2 0.18033688011112042f      // ATT_SCALE * log2(e)
#define EPSV 1e-5f

// ---------------- scratch (static device allocations are allowed) -----------
#define XN (BB*SS*CC)     // 5242880
#define WN (CC*CC)        // 1638400
__device__ float g_tf[XN + 4*WN];     // tf32-rounded [X | Wq | Wk | Wv | Wo]
__device__ float g_q[BB*SS*CC];
__device__ float g_k[BB*SS*CC];
__device__ float g_v[BB*SS*CC];
__device__ float g_vt[BB*SS*CC];      // V transposed (tf32-rounded): [b][h][d][s]
__device__ float g_attn[BB*SS*CC];    // tf32-rounded attention output
__device__ float g_psum[2*BB*16*CC];  // stats partials: [z][b][seg][c]
__device__ float g_psq [2*BB*16*CC];
__device__ float g_scl[2*BB*CC];
__device__ float g_shf[2*BB*CC];

// =================== helpers (sm_75+/sm_80+ PTX, base-target safe) =========
__device__ __forceinline__ uint32_t f2tf32(float x) {
    uint32_t r;
    asm("cvt.rna.tf32.f32 %0, %1;" : "=r"(r) : "f"(x));
    return r;
}

__device__ __forceinline__ float fexp2(float x) {
    float y;
    asm("ex2.approx.f32 %0, %1;" : "=f"(y) : "f"(x));
    return y;
}

__device__ __forceinline__ void mma_1688(
    float c[4], const uint32_t a[4], uint32_t b0, uint32_t b1)
{
    asm volatile(
        "mma.sync.aligned.m16n8k8.row.col.f32.tf32.tf32.f32 "
        "{%0,%1,%2,%3}, {%4,%5,%6,%7}, {%8,%9}, {%0,%1,%2,%3};\n"
        : "+f"(c[0]), "+f"(c[1]), "+f"(c[2]), "+f"(c[3])
        : "r"(a[0]), "r"(a[1]), "r"(a[2]), "r"(a[3]), "r"(b0), "r"(b1));
}

__device__ __forceinline__ uint32_t smem_u32(const void* p) {
    uint32_t a;
    asm("{ .reg .u64 t; cvta.to.shared.u64 t, %1; cvt.u32.u64 %0, t; }"
        : "=r"(a) : "l"(p));
    return a;
}

#define LDSM_X4(R, addr) \
    asm volatile("ldmatrix.sync.aligned.m8n8.x4.shared.b16 {%0,%1,%2,%3}, [%4];" \
        : "=r"((R)[0]), "=r"((R)[1]), "=r"((R)[2]), "=r"((R)[3]) : "r"(addr))

#define CP_ASYNC16(dst, src) \
    asm volatile("cp.async.cg.shared.global [%0], [%1], 16;" \
        :: "r"(dst), "l"(src))
#define CP_COMMIT() asm volatile("cp.async.commit_group;")
#define CP_WAIT1()  asm volatile("cp.async.wait_group 1;")

// ---------------------------------------------------------------------------
// tf32 pre-rounding pass over [X | Wq | Wk | Wv | Wo]
// ---------------------------------------------------------------------------
#define CVT_F4 ((XN + 4*WN) / 4)
__global__ __launch_bounds__(256) void k_cvt(
    const float* __restrict__ X,  const float* __restrict__ Wq,
    const float* __restrict__ Wk, const float* __restrict__ Wv,
    const float* __restrict__ Wo)
{
    int i4 = blockIdx.x * 256 + threadIdx.x;
    if (i4 >= CVT_F4) return;
    const float* src;
    int base;
    if      (i4 < XN/4)          { src = X;  base = 0; }
    else if (i4 < (XN+WN)/4)     { src = Wq; base = XN/4; }
    else if (i4 < (XN+2*WN)/4)   { src = Wk; base = (XN+WN)/4; }
    else if (i4 < (XN+3*WN)/4)   { src = Wv; base = (XN+2*WN)/4; }
    else                         { src = Wo; base = (XN+3*WN)/4; }
    float4 v = ((const float4*)src)[i4 - base];
    uint4 t = make_uint4(f2tf32(v.x), f2tf32(v.y), f2tf32(v.z), f2tf32(v.w));
    ((uint4*)g_tf)[i4] = t;
}

// ---------------------------------------------------------------------------
// Tensor-core tf32 GEMM, batched-LDSM fragments, 3-stage cp.async pipeline,
// ONE barrier per k-tile. Block 128x128, BK=16, 256 threads / 8 warps.
// ---------------------------------------------------------------------------
#define BKP 20
#define GKT (CC / 16)   // 80 k-tiles
#define GST 10240       // bytes per operand-stage
#define GBOFF 30720     // B region offset
#define GEMM_SMEM 61440

#define GISSUE(t, s) do { \
    uint32_t _da = base + (s) * GST + stoff; \
    uint32_t _db = base + GBOFF + (s) * GST + stoff; \
    const float* _An = Ap + (t) * 16; \
    const float* _Bn = Bp + (t) * 16; \
    CP_ASYNC16(_da,      _An); \
    CP_ASYNC16(_da + 16, _An + 4); \
    CP_ASYNC16(_db,      _Bn); \
    CP_ASYNC16(_db + 16, _Bn + 4); \
} while (0)

__device__ __forceinline__ void gemm_mma_body(
    const float* __restrict__ A, const float* __restrict__ W,
    const float* __restrict__ bias, float* __restrict__ Cout)
{
    extern __shared__ __align__(16) uint32_t gsm[];

    const int tid  = threadIdx.x;
    const int warp = tid >> 5, lane = tid & 31;
    const int wm   = (warp & 3) * 32;
    const int wn   = (warp >> 2) * 64;
    const int tg   = lane & 3, gid = lane >> 2;
    const int m0   = blockIdx.y * 128;
    const int n0   = blockIdx.x * 128;

    const int lrow = tid >> 1;
    const int lc   = (tid & 1) * 8;
    const float* Ap = A + (size_t)(m0 + lrow) * CC + lc;
    const float* Bp = W + (size_t)(n0 + lrow) * CC + lc;

    const uint32_t base  = smem_u32(gsm);
    const uint32_t stoff = (uint32_t)(lrow * BKP + lc) * 4;

    const int lr = lane & 7;
    const uint32_t aoff = ((wm + ((lane >> 3) & 1) * 8 + lr) * BKP
                           + ((lane >> 4) & 1) * 4) * 4;
    const uint32_t boff = ((wn + (lane >> 4) * 8 + lr) * BKP
                           + ((lane >> 3) & 1) * 4) * 4;

    float acc[2][8][4];
#pragma unroll
    for (int im = 0; im < 2; im++)
#pragma unroll
        for (int in_ = 0; in_ < 8; in_++)
#pragma unroll
            for (int r = 0; r < 4; r++) acc[im][in_][r] = 0.f;

    GISSUE(0, 0); CP_COMMIT();
    GISSUE(1, 1); CP_COMMIT();

    int cs = 0;
    for (int kt = 0; kt < GKT; kt++) {
        CP_WAIT1();
        __syncthreads();

        int is_ = cs + 2; if (is_ >= 3) is_ -= 3;
        if (kt + 2 < GKT) GISSUE(kt + 2, is_);
        CP_COMMIT();

        const uint32_t sal = base + cs * GST + aoff;
        const uint32_t sbl = base + GBOFF + cs * GST + boff;
#pragma unroll
        for (int ks = 0; ks < 16; ks += 8) {
            // batch ALL fragment loads for this k-half, then all mma
            uint32_t af[2][4];
            uint32_t bf[4][4];
            LDSM_X4(af[0], sal + ks * 4);
            LDSM_X4(af[1], sal + 16 * BKP * 4 + ks * 4);
#pragma unroll
            for (int np = 0; np < 4; np++)
                LDSM_X4(bf[np], sbl + np * 16 * BKP * 4 + ks * 4);
#pragma unroll
            for (int np = 0; np < 4; np++) {
                mma_1688(acc[0][2*np],     af[0], bf[np][0], bf[np][1]);
                mma_1688(acc[0][2*np + 1], af[0], bf[np][2], bf[np][3]);
                mma_1688(acc[1][2*np],     af[1], bf[np][0], bf[np][1]);
                mma_1688(acc[1][2*np + 1], af[1], bf[np][2], bf[np][3]);
            }
        }
        if (++cs == 3) cs = 0;
    }

#pragma unroll
    for (int im = 0; im < 2; im++) {
        int row = m0 + wm + im * 16 + gid;
#pragma unroll
        for (int in_ = 0; in_ < 8; in_++) {
            int col = n0 + wn + in_ * 8 + tg * 2;
            float b0v = 0.f, b1v = 0.f;
            if (bias) { b0v = bias[col]; b1v = bias[col + 1]; }
            float2 lo = make_float2(acc[im][in_][0] + b0v, acc[im][in_][1] + b1v);
            float2 hi = make_float2(acc[im][in_][2] + b0v, acc[im][in_][3] + b1v);
            *(float2*)(Cout + (size_t)row * CC + col)       = lo;
            *(float2*)(Cout + (size_t)(row + 8) * CC + col) = hi;
        }
    }
}

__global__ __launch_bounds__(256) void k_qkv_mma()
{
    const float* X = g_tf;
    const float* W = g_tf + XN + (size_t)blockIdx.z * WN;
    float* O;
    if (blockIdx.z == 0)      O = g_q;
    else if (blockIdx.z == 1) O = g_k;
    else                      O = g_v;
    gemm_mma_body(X, W, nullptr, O);
}

__global__ __launch_bounds__(256) void k_proj_mma(
    const float* __restrict__ bo, float* __restrict__ out)
{
    gemm_mma_body(g_attn, g_tf + XN + 3 * (size_t)WN, bo, out);
}

// ---------------------------------------------------------------------------
// V transpose + tf32 round: g_v [b][s][h][d] -> g_vt [b][h][d][s]
// ---------------------------------------------------------------------------
__global__ __launch_bounds__(256) void k_transv()
{
    __shared__ float tile[32][33];
    const int bh = blockIdx.z;
    const int b  = bh / HH, h = bh % HH;
    const int s0 = blockIdx.x * 32;
    const int d0 = blockIdx.y * 32;
    const int tx = threadIdx.x, ty = threadIdx.y;

    const float* src = g_v + (size_t)(b * SS + s0) * CC + h * DD + d0;
#pragma unroll
    for (int j = 0; j < 32; j += 8)
        tile[ty + j][tx] = src[(size_t)(ty + j) * CC + tx];
    __syncthreads();

    float* dst = g_vt + ((size_t)(b * HH + h) * DD + d0) * SS + s0;
#pragma unroll
    for (int j = 0; j < 32; j += 8)
        dst[(size_t)(ty + j) * SS + tx] = __uint_as_float(f2tf32(tile[tx][ty + j]));
}

// ---------------------------------------------------------------------------
// AdaIN stats: split-S partials (16 segments of 64 rows).
// ---------------------------------------------------------------------------
__global__ void k_stats()
{
    const int c   = blockIdx.x * 128 + threadIdx.x;
    const int b   = blockIdx.y;
    const int z   = blockIdx.z >> 4;
    const int seg = blockIdx.z & 15;
    const float* src = z ? g_k : g_q;
    const float* p = src + ((size_t)b * SS + seg * 64) * CC + c;

    float s0 = 0, s1 = 0, q0 = 0, q1 = 0;
#pragma unroll 4
    for (int s = 0; s < 64; s += 2) {
        float x0 = p[(size_t)(s + 0) * CC];
        float x1 = p[(size_t)(s + 1) * CC];
        s0 += x0; q0 = fmaf(x0, x0, q0);
        s1 += x1; q1 = fmaf(x1, x1, q1);
    }
    int idx = ((z * BB + b) * 16 + seg) * CC + c;
    g_psum[idx] = s0 + s1;
    g_psq [idx] = q0 + q1;
}

__global__ void k_finalize()
{
    int i = blockIdx.x * 256 + threadIdx.x;   // (z*BB+b)*CC + c
    if (i >= 2 * BB * CC) return;
    int c  = i % CC;
    int b  = (i / CC) % BB;
    int z  = i / (CC * BB);
    int sb = (b < BB / 2) ? 0 : BB / 2;

    float sum = 0, sq = 0, sums = 0, sqs = 0;
#pragma unroll
    for (int seg = 0; seg < 16; seg++) {
        sum  += g_psum[((z * BB + b)  * 16 + seg) * CC + c];
        sq   += g_psq [((z * BB + b)  * 16 + seg) * CC + c];
        sums += g_psum[((z * BB + sb) * 16 + seg) * CC + c];
        sqs  += g_psq [((z * BB + sb) * 16 + seg) * CC + c];
    }
    float mean  = sum  * (1.0f / SS);
    float means = sums * (1.0f / SS);
    float sd  = sqrtf((sq  - sum  * mean ) * (1.0f / (SS - 1)) + EPSV);
    float sds = sqrtf((sqs - sums * means) * (1.0f / (SS - 1)) + EPSV);
    float scl = sds / sd;
    g_scl[i] = scl;
    g_shf[i] = means - mean * scl;
}

__global__ void k_apply()
{
    const int TOT4  = 2 * BB * SS * CC / 4;
    const int per_t = SS * CC / 4;
    int i4 = blockIdx.x * 256 + threadIdx.x;
    if (i4 >= TOT4) return;
    int zb = i4 / per_t;
    int r  = i4 % per_t;
    int c  = (r % (CC / 4)) * 4;
    float* buf = (zb < BB) ? g_q : g_k;
    int b = zb & 3;
    float4* p = (float4*)buf + (size_t)b * per_t + r;
    float4 scl = *(const float4*)&g_scl[zb * CC + c];
    float4 shf = *(const float4*)&g_shf[zb * CC + c];
    float4 x = *p;
    uint4 t;
    t.x = f2tf32(fmaf(x.x, scl.x, shf.x));
    t.y = f2tf32(fmaf(x.y, scl.y, shf.y));
    t.z = f2tf32(fmaf(x.z, scl.z, shf.z));
    t.w = f2tf32(fmaf(x.w, scl.w, shf.w));
    *(uint4*)p = t;
}

// ---------------------------------------------------------------------------
// Flash attention on tensor cores. 3-stage cp.async ring, one barrier per
// chunk, shuffle-built P fragments, batched LDSM before each mma group.
// Style dedup: self-style batches run 16 chunks. Max-free softmax (exp2).
// CTA: 128 queries of one (b,h). 8 warps x 16 q-rows. Chunks of 64 keys.
// ---------------------------------------------------------------------------
#define FP 68                       // smem pitch (words), 68 % 32 == 4
#define KS_OFF(s) ((s) * 128 * FP)
#define VS_OFF(s) ((s) * 128 * FP + 64 * FP)
#define ATT_SMEM  (3 * 128 * FP * 4)    // 104448 bytes

__global__ __launch_bounds__(256, 2) void k_attn_mma()
{
    extern __shared__ uint32_t sm[];

    const int tid  = threadIdx.x;
    const int warp = tid >> 5, lane = tid & 31;
    const int tg   = lane & 3, gid = lane >> 2;

    // remap: groups {0,1,2,3} -> batches {1,3,0,2}; long CTAs first
    const int yb = blockIdx.y;
    const int h  = yb % HH;
    const int grp = yb / HH;
    const int b  = (grp == 0) ? 1 : (grp == 1) ? 3 : (grp == 2) ? 0 : 2;

    const int q0   = blockIdx.x * 128;
    const int sbv  = (b < BB / 2) ? 0 : BB / 2;
    const int nch  = (b == sbv) ? 16 : 32;   // dedup for self-style batches
    const int wq   = warp * 16;

    const uint32_t smb = smem_u32(sm);
    const int frow = tid >> 4, fc4 = tid & 15;

    const int lr = lane & 7;
    const uint32_t aoff = ((wq + ((lane >> 3) & 1) * 8 + lr) * FP
                           + ((lane >> 4) & 1) * 4) * 4;
    const uint32_t kvoff = (((lane >> 4) * 8 + lr) * FP
                           + ((lane >> 3) & 1) * 4) * 4;

    // shfl source lanes for P-fragment construction
    const int ps1 = (lane & 0x1C) | (tg >> 1);   // 4*gid + (tg>>1)
    const int ps2 = ps1 + 2;
    const int todd = tg & 1;

    // ---- stage Q tile through stage-0 region, grab frags ----
    {
        const float* Qg = g_q + (size_t)(b * SS + q0) * CC + h * DD;
#pragma unroll
        for (int i = 0; i < 8; i++) {
            int fid = tid + i * 256;
            int row = fid >> 4, c4 = fid & 15;
            *(uint4*)(sm + row * FP + c4 * 4) =
                *(const uint4*)(Qg + (size_t)row * CC + c4 * 4);
        }
    }
    __syncthreads();

    uint32_t qf[8][4];
#pragma unroll
    for (int ks = 0; ks < 8; ks++) LDSM_X4(qf[ks], smb + aoff + ks * 32);
    __syncthreads();   // Q reads done; stage 0 free for chunk 0

    float o[8][4];
#pragma unroll
    for (int n_ = 0; n_ < 8; n_++)
#pragma unroll
        for (int r = 0; r < 4; r++) o[n_][r] = 0.f;
    float l0r = 0.f, l1r = 0.f;

    const float* Kbase0 = g_k + (size_t)b * SS * CC + h * DD;
    const float* Kbase1 = g_k + (size_t)sbv * SS * CC + h * DD;
    const float* Vbase0 = g_vt + ((size_t)(b * HH + h) * DD) * SS;
    const float* Vbase1 = g_vt + ((size_t)(sbv * HH + h) * DD) * SS;

#define AISSUE(c, s) do { \
    const int _self = ((c) < 16); \
    const int _kr   = (_self ? (c) : (c) - 16) * 64; \
    const float* _Kg = (_self ? Kbase0 : Kbase1) + (size_t)_kr * CC; \
    const float* _Vg = (_self ? Vbase0 : Vbase1) + _kr; \
    uint32_t _kd = smb + (KS_OFF(s) + frow * FP + fc4 * 4) * 4; \
    uint32_t _vd = smb + (VS_OFF(s) + frow * FP + fc4 * 4) * 4; \
    _Pragma("unroll") \
    for (int _i = 0; _i < 4; _i++) { \
        int _row = frow + _i * 16; \
        CP_ASYNC16(_kd + _i * 16 * FP * 4, _Kg + (size_t)_row * CC + fc4 * 4); \
        CP_ASYNC16(_vd + _i * 16 * FP * 4, _Vg + (size_t)_row * SS + fc4 * 4); \
    } \
} while (0)

    // prologue: chunks 0,1 -> stages 0,1
    AISSUE(0, 0); CP_COMMIT();
    AISSUE(1, 1); CP_COMMIT();

    int st = 0;
    for (int ch = 0; ch < nch; ch++) {
        const float b2 = (ch < 16) ? 0.f : 1.0f;   // log2(e)*ln2 == 1

        CP_WAIT1();
        __syncthreads();   // chunk ch visible; refill target's readers done

        int is_ = st + 2; if (is_ >= 3) is_ -= 3;
        if (ch + 2 < nch) AISSUE(ch + 2, is_);
        CP_COMMIT();

        const uint32_t kbase = smb + KS_OFF(st) * 4 + kvoff;
        const uint32_t vbase = smb + VS_OFF(st) * 4 + kvoff;

        // ---- S = Q @ K^T  (16 x 64 per warp), batched LDSM per ks ----
        float sacc[8][4];
#pragma unroll
        for (int n_ = 0; n_ < 8; n_++)
#pragma unroll
            for (int r = 0; r < 4; r++) sacc[n_][r] = 0.f;

#pragma unroll
        for (int ks = 0; ks < 8; ks++) {
            uint32_t bf[4][4];
#pragma unroll
            for (int np = 0; np < 4; np++)
                LDSM_X4(bf[np], kbase + np * 16 * FP * 4 + ks * 32);
#pragma unroll
            for (int np = 0; np < 4; np++) {
                mma_1688(sacc[2*np],     qf[ks], bf[np][0], bf[np][1]);
                mma_1688(sacc[2*np + 1], qf[ks], bf[np][2], bf[np][3]);
            }
        }

        // ---- softmax phase: convert sacc -> P fragments IN PLACE ----
        uint32_t* pacc = (uint32_t*)sacc;
#pragma unroll
        for (int kb = 0; kb < 8; kb++) {
            float e0 = fexp2(fmaf(sacc[kb][0], SC2, b2));
            float e1 = fexp2(fmaf(sacc[kb][1], SC2, b2));
            float e2 = fexp2(fmaf(sacc[kb][2], SC2, b2));
            float e3 = fexp2(fmaf(sacc[kb][3], SC2, b2));
            l0r += e0 + e1;
            l1r += e2 + e3;
            uint32_t p0 = f2tf32(e0), p1 = f2tf32(e1);
            uint32_t p2 = f2tf32(e2), p3 = f2tf32(e3);

            uint32_t x0 = __shfl_sync(0xffffffffu, p0, ps1);
            uint32_t x1 = __shfl_sync(0xffffffffu, p1, ps1);
            uint32_t f0 = todd ? x1 : x0;
            uint32_t y0 = __shfl_sync(0xffffffffu, p2, ps1);
            uint32_t y1 = __shfl_sync(0xffffffffu, p3, ps1);
            uint32_t f1 = todd ? y1 : y0;
            uint32_t x2 = __shfl_sync(0xffffffffu, p0, ps2);
            uint32_t x3 = __shfl_sync(0xffffffffu, p1, ps2);
            uint32_t f2_ = todd ? x3 : x2;
            uint32_t y2 = __shfl_sync(0xffffffffu, p2, ps2);
            uint32_t y3 = __shfl_sync(0xffffffffu, p3, ps2);
            uint32_t f3 = todd ? y3 : y2;
            pacc[kb * 4 + 0] = f0;
            pacc[kb * 4 + 1] = f1;
            pacc[kb * 4 + 2] = f2_;
            pacc[kb * 4 + 3] = f3;
        }

        // ---- O += P @ V, batched LDSM per kb ----
#pragma unroll
        for (int kb = 0; kb < 8; kb++) {
            uint32_t bf[4][4];
#pragma unroll
            for (int np = 0; np < 4; np++)
                LDSM_X4(bf[np], vbase + np * 16 * FP * 4 + kb * 32);
#pragma unroll
            for (int np = 0; np < 4; np++) {
                mma_1688(o[2*np],     &pacc[kb * 4], bf[np][0], bf[np][1]);
                mma_1688(o[2*np + 1], &pacc[kb * 4], bf[np][2], bf[np][3]);
            }
        }

        if (++st == 3) st = 0;
    }

    // ---- epilogue: quad-reduce row sums, normalize, store ----
    l0r += __shfl_xor_sync(0xffffffffu, l0r, 1);
    l0r += __shfl_xor_sync(0xffffffffu, l0r, 2);
    l1r += __shfl_xor_sync(0xffffffffu, l1r, 1);
    l1r += __shfl_xor_sync(0xffffffffu, l1r, 2);
    const float inv0 = 1.0f / l0r, inv1 = 1.0f / l1r;
    float* Og = g_attn + (size_t)(b * SS + q0 + wq) * CC + h * DD;
#pragma unroll
    for (int n_ = 0; n_ < 8; n_++) {
        int col = n_ * 8 + tg * 2;
        uint2 lo = make_uint2(f2tf32(o[n_][0] * inv0), f2tf32(o[n_][1] * inv0));
        uint2 hi = make_uint2(f2tf32(o[n_][2] * inv1), f2tf32(o[n_][3] * inv1));
        *(uint2*)(Og + (size_t)gid * CC + col)       = lo;
        *(uint2*)(Og + (size_t)(gid + 8) * CC + col) = hi;
    }
}

// ---------------------------------------------------------------------------
extern "C" void kernel_launch(void* const* d_in, const int* in_sizes, int n_in,
                              void* d_out, int out_size)
{
    (void)in_sizes; (void)n_in; (void)out_size;
    const float* X  = (const float*)d_in[0];
    const float* Wq = (const float*)d_in[1];
    const float* Wk = (const float*)d_in[2];
    const float* Wv = (const float*)d_in[3];
    const float* Wo = (const float*)d_in[4];
    const float* bo = (const float*)d_in[5];
    float* out = (float*)d_out;

    cudaFuncSetAttribute(k_attn_mma, cudaFuncAttributeMaxDynamicSharedMemorySize,
                         ATT_SMEM);
    cudaFuncSetAttribute(k_qkv_mma, cudaFuncAttributeMaxDynamicSharedMemorySize,
                         GEMM_SMEM);
    cudaFuncSetAttribute(k_proj_mma, cudaFuncAttributeMaxDynamicSharedMemorySize,
                         GEMM_SMEM);

    k_cvt<<<(CVT_F4 + 255) / 256, 256>>>(X, Wq, Wk, Wv, Wo);
    k_qkv_mma<<<dim3(CC / 128, (BB * SS) / 128, 3), 256, GEMM_SMEM>>>();
    k_transv<<<dim3(SS / 32, DD / 32, BB * HH), dim3(32, 8)>>>();
    k_stats<<<dim3(CC / 128, BB, 32), 128>>>();
    k_finalize<<<(2 * BB * CC + 255) / 256, 256>>>();
    k_apply<<<(2 * BB * SS * CC / 4 + 255) / 256, 256>>>();
    k_attn_mma<<<dim3(SS / 128, BB * HH), 256, ATT_SMEM>>>();
    k_proj_mma<<<dim3(CC / 128, (BB * SS) / 128), 256, GEMM_SMEM>>>(bo, out);
}

// round 13
// speedup vs baseline: 1.9045x; 1.9045x over previous
#include <cuda_runtime.h>
#include <cuda_fp16.h>
#include <cstdint>
#include <math.h>

// Problem constants
#define BB 4
#define SS 1024
#define CC 1280
#define HH 20
#define DD 64
#define SC2 0.18033688011112042f      // 64^-0.5 * log2(e)
#define EPSV 1e-5f

// ---------------- scratch (static device allocations are allowed) -----------
#define XN (BB*SS*CC)     // 5242880
#define WN (CC*CC)        // 1638400
__device__ __half g_xh[XN + 4*WN];    // fp16 [X | Wq | Wk | Wv | Wo]
__device__ float  g_q[BB*SS*CC];      // fp32 Q (pre-AdaIN, for stats)
__device__ float  g_k[BB*SS*CC];      // fp32 K
__device__ float  g_v[BB*SS*CC];      // fp32 V
__device__ __half g_qh[BB*SS*CC];     // fp16 AdaIN'd Q
__device__ __half g_kh[BB*SS*CC];     // fp16 AdaIN'd K
__device__ __half g_vth[BB*SS*CC];    // fp16 V transposed: [b][h][d][s]
__device__ __half g_attnh[BB*SS*CC];  // fp16 attention output
__device__ float  g_psum[2*BB*16*CC];
__device__ float  g_psq [2*BB*16*CC];
__device__ float  g_scl[2*BB*CC];
__device__ float  g_shf[2*BB*CC];

// =================== helpers (sm_75+/sm_80+ PTX, base-target safe) =========
__device__ __forceinline__ float fexp2(float x) {
    float y;
    asm("ex2.approx.f32 %0, %1;" : "=f"(y) : "f"(x));
    return y;
}

__device__ __forceinline__ void mma_16816(
    float c[4], const uint32_t a[4], uint32_t b0, uint32_t b1)
{
    asm volatile(
        "mma.sync.aligned.m16n8k16.row.col.f32.f16.f16.f32 "
        "{%0,%1,%2,%3}, {%4,%5,%6,%7}, {%8,%9}, {%0,%1,%2,%3};\n"
        : "+f"(c[0]), "+f"(c[1]), "+f"(c[2]), "+f"(c[3])
        : "r"(a[0]), "r"(a[1]), "r"(a[2]), "r"(a[3]), "r"(b0), "r"(b1));
}

__device__ __forceinline__ uint32_t smem_u32(const void* p) {
    uint32_t a;
    asm("{ .reg .u64 t; cvta.to.shared.u64 t, %1; cvt.u32.u64 %0, t; }"
        : "=r"(a) : "l"(p));
    return a;
}

__device__ __forceinline__ uint32_t pack_h2(float a, float b) {
    __half2 t = __floats2half2_rn(a, b);
    return *(uint32_t*)&t;
}

#define LDSM_X4(R, addr) \
    asm volatile("ldmatrix.sync.aligned.m8n8.x4.shared.b16 {%0,%1,%2,%3}, [%4];" \
        : "=r"((R)[0]), "=r"((R)[1]), "=r"((R)[2]), "=r"((R)[3]) : "r"(addr))

#define CP_ASYNC16(dst, src) \
    asm volatile("cp.async.cg.shared.global [%0], [%1], 16;" \
        :: "r"(dst), "l"(src))
#define CP_COMMIT() asm volatile("cp.async.commit_group;")
#define CP_WAIT1()  asm volatile("cp.async.wait_group 1;")

// ---------------------------------------------------------------------------
// fp16 conversion pass over [X | Wq | Wk | Wv | Wo]
// ---------------------------------------------------------------------------
#define CVT_F4 ((XN + 4*WN) / 4)
__global__ __launch_bounds__(256) void k_cvt(
    const float* __restrict__ X,  const float* __restrict__ Wq,
    const float* __restrict__ Wk, const float* __restrict__ Wv,
    const float* __restrict__ Wo)
{
    int i4 = blockIdx.x * 256 + threadIdx.x;
    if (i4 >= CVT_F4) return;
    const float* src;
    int base;
    if      (i4 < XN/4)          { src = X;  base = 0; }
    else if (i4 < (XN+WN)/4)     { src = Wq; base = XN/4; }
    else if (i4 < (XN+2*WN)/4)   { src = Wk; base = (XN+WN)/4; }
    else if (i4 < (XN+3*WN)/4)   { src = Wv; base = (XN+2*WN)/4; }
    else                         { src = Wo; base = (XN+3*WN)/4; }
    float4 v = ((const float4*)src)[i4 - base];
    uint2 t;
    t.x = pack_h2(v.x, v.y);
    t.y = pack_h2(v.z, v.w);
    ((uint2*)g_xh)[i4] = t;
}

// ---------------------------------------------------------------------------
// Tensor-core fp16 GEMM (fp32 accum): C = A @ W^T (+bias). Inputs fp16.
// Block 128x128, BK=32 fp16, 3-stage cp.async, one barrier per k-tile.
// Smem pitch 40 fp16 (80 B). Stage = 10240 B per operand.
// ---------------------------------------------------------------------------
#define GKT (CC / 32)   // 40 k-tiles
#define GST 10240
#define GBOFF 30720
#define GEMM_SMEM 61440

#define GISSUE(t, s) do { \
    uint32_t _da = base + (s) * GST + stoff; \
    uint32_t _db = base + GBOFF + (s) * GST + stoff; \
    const __half* _An = Ap + (t) * 32; \
    const __half* _Bn = Bp + (t) * 32; \
    CP_ASYNC16(_da,      _An); \
    CP_ASYNC16(_da + 16, _An + 8); \
    CP_ASYNC16(_db,      _Bn); \
    CP_ASYNC16(_db + 16, _Bn + 8); \
} while (0)

__device__ __forceinline__ void gemm_mma_body(
    const __half* __restrict__ A, const __half* __restrict__ W,
    const float* __restrict__ bias, float* __restrict__ Cout)
{
    extern __shared__ __align__(16) uint32_t gsm[];

    const int tid  = threadIdx.x;
    const int warp = tid >> 5, lane = tid & 31;
    const int wm   = (warp & 3) * 32;
    const int wn   = (warp >> 2) * 64;
    const int tg   = lane & 3, gid = lane >> 2;
    const int m0   = blockIdx.y * 128;
    const int n0   = blockIdx.x * 128;

    const int lrow = tid >> 1;
    const int lc   = (tid & 1) * 16;
    const __half* Ap = A + (size_t)(m0 + lrow) * CC + lc;
    const __half* Bp = W + (size_t)(n0 + lrow) * CC + lc;

    const uint32_t base  = smem_u32(gsm);
    const uint32_t stoff = (uint32_t)(lrow * 40 + lc) * 2;

    const int lr = lane & 7;
    const uint32_t aoff = ((wm + ((lane >> 3) & 1) * 8 + lr) * 40
                           + ((lane >> 4) & 1) * 8) * 2;
    const uint32_t boff = ((wn + (lane >> 4) * 8 + lr) * 40
                           + ((lane >> 3) & 1) * 8) * 2;

    float acc[2][8][4];
#pragma unroll
    for (int im = 0; im < 2; im++)
#pragma unroll
        for (int in_ = 0; in_ < 8; in_++)
#pragma unroll
            for (int r = 0; r < 4; r++) acc[im][in_][r] = 0.f;

    GISSUE(0, 0); CP_COMMIT();
    GISSUE(1, 1); CP_COMMIT();

    int cs = 0;
    for (int kt = 0; kt < GKT; kt++) {
        CP_WAIT1();
        __syncthreads();

        int is_ = cs + 2; if (is_ >= 3) is_ -= 3;
        if (kt + 2 < GKT) GISSUE(kt + 2, is_);
        CP_COMMIT();

        const uint32_t sal = base + cs * GST + aoff;
        const uint32_t sbl = base + GBOFF + cs * GST + boff;
#pragma unroll
        for (int ks = 0; ks < 2; ks++) {          // two k16 steps per BK=32
            uint32_t af[2][4];
            uint32_t bf[4][4];
            LDSM_X4(af[0], sal + ks * 32);
            LDSM_X4(af[1], sal + 16 * 80 + ks * 32);
#pragma unroll
            for (int np = 0; np < 4; np++)
                LDSM_X4(bf[np], sbl + np * 16 * 80 + ks * 32);
#pragma unroll
            for (int np = 0; np < 4; np++) {
                mma_16816(acc[0][2*np],     af[0], bf[np][0], bf[np][1]);
                mma_16816(acc[0][2*np + 1], af[0], bf[np][2], bf[np][3]);
                mma_16816(acc[1][2*np],     af[1], bf[np][0], bf[np][1]);
                mma_16816(acc[1][2*np + 1], af[1], bf[np][2], bf[np][3]);
            }
        }
        if (++cs == 3) cs = 0;
    }

#pragma unroll
    for (int im = 0; im < 2; im++) {
        int row = m0 + wm + im * 16 + gid;
#pragma unroll
        for (int in_ = 0; in_ < 8; in_++) {
            int col = n0 + wn + in_ * 8 + tg * 2;
            float b0v = 0.f, b1v = 0.f;
            if (bias) { b0v = bias[col]; b1v = bias[col + 1]; }
            float2 lo = make_float2(acc[im][in_][0] + b0v, acc[im][in_][1] + b1v);
            float2 hi = make_float2(acc[im][in_][2] + b0v, acc[im][in_][3] + b1v);
            *(float2*)(Cout + (size_t)row * CC + col)       = lo;
            *(float2*)(Cout + (size_t)(row + 8) * CC + col) = hi;
        }
    }
}

__global__ __launch_bounds__(256) void k_qkv_mma()
{
    const __half* X = g_xh;
    const __half* W = g_xh + XN + (size_t)blockIdx.z * WN;
    float* O;
    if (blockIdx.z == 0)      O = g_q;
    else if (blockIdx.z == 1) O = g_k;
    else                      O = g_v;
    gemm_mma_body(X, W, nullptr, O);
}

__global__ __launch_bounds__(256) void k_proj_mma(
    const float* __restrict__ bo, float* __restrict__ out)
{
    gemm_mma_body(g_attnh, g_xh + XN + 3 * (size_t)WN, bo, out);
}

// ---------------------------------------------------------------------------
// V transpose + fp16: g_v [b][s][h][d] -> g_vth [b][h][d][s]
// ---------------------------------------------------------------------------
__global__ __launch_bounds__(256) void k_transv()
{
    __shared__ float tile[32][33];
    const int bh = blockIdx.z;
    const int b  = bh / HH, h = bh % HH;
    const int s0 = blockIdx.x * 32;
    const int d0 = blockIdx.y * 32;
    const int tx = threadIdx.x, ty = threadIdx.y;

    const float* src = g_v + (size_t)(b * SS + s0) * CC + h * DD + d0;
#pragma unroll
    for (int j = 0; j < 32; j += 8)
        tile[ty + j][tx] = src[(size_t)(ty + j) * CC + tx];
    __syncthreads();

    __half* dst = g_vth + ((size_t)(b * HH + h) * DD + d0) * SS + s0;
#pragma unroll
    for (int j = 0; j < 32; j += 8)
        dst[(size_t)(ty + j) * SS + tx] = __float2half_rn(tile[tx][ty + j]);
}

// ---------------------------------------------------------------------------
// AdaIN stats (split-S, 16 segments) / finalize / apply (fp16 out)
// ---------------------------------------------------------------------------
__global__ void k_stats()
{
    const int c   = blockIdx.x * 128 + threadIdx.x;
    const int b   = blockIdx.y;
    const int z   = blockIdx.z >> 4;
    const int seg = blockIdx.z & 15;
    const float* src = z ? g_k : g_q;
    const float* p = src + ((size_t)b * SS + seg * 64) * CC + c;

    float s0 = 0, s1 = 0, q0 = 0, q1 = 0;
#pragma unroll 4
    for (int s = 0; s < 64; s += 2) {
        float x0 = p[(size_t)(s + 0) * CC];
        float x1 = p[(size_t)(s + 1) * CC];
        s0 += x0; q0 = fmaf(x0, x0, q0);
        s1 += x1; q1 = fmaf(x1, x1, q1);
    }
    int idx = ((z * BB + b) * 16 + seg) * CC + c;
    g_psum[idx] = s0 + s1;
    g_psq [idx] = q0 + q1;
}

__global__ void k_finalize()
{
    int i = blockIdx.x * 256 + threadIdx.x;
    if (i >= 2 * BB * CC) return;
    int c  = i % CC;
    int b  = (i / CC) % BB;
    int z  = i / (CC * BB);
    int sb = (b < BB / 2) ? 0 : BB / 2;

    float sum = 0, sq = 0, sums = 0, sqs = 0;
#pragma unroll
    for (int seg = 0; seg < 16; seg++) {
        sum  += g_psum[((z * BB + b)  * 16 + seg) * CC + c];
        sq   += g_psq [((z * BB + b)  * 16 + seg) * CC + c];
        sums += g_psum[((z * BB + sb) * 16 + seg) * CC + c];
        sqs  += g_psq [((z * BB + sb) * 16 + seg) * CC + c];
    }
    float mean  = sum  * (1.0f / SS);
    float means = sums * (1.0f / SS);
    float sd  = sqrtf((sq  - sum  * mean ) * (1.0f / (SS - 1)) + EPSV);
    float sds = sqrtf((sqs - sums * means) * (1.0f / (SS - 1)) + EPSV);
    float scl = sds / sd;
    g_scl[i] = scl;
    g_shf[i] = means - mean * scl;
}

__global__ void k_apply()
{
    const int TOT4  = 2 * BB * SS * CC / 4;
    const int per_t = SS * CC / 4;
    int i4 = blockIdx.x * 256 + threadIdx.x;
    if (i4 >= TOT4) return;
    int zb = i4 / per_t;
    int r  = i4 % per_t;
    int c  = (r % (CC / 4)) * 4;
    const float* fb = (zb < BB) ? g_q : g_k;
    __half*      hb = (zb < BB) ? g_qh : g_kh;
    int b = zb & 3;
    float4 x = ((const float4*)(fb + (size_t)b * SS * CC))[r];
    float4 scl = *(const float4*)&g_scl[zb * CC + c];
    float4 shf = *(const float4*)&g_shf[zb * CC + c];
    uint2 t;
    t.x = pack_h2(fmaf(x.x, scl.x, shf.x), fmaf(x.y, scl.y, shf.y));
    t.y = pack_h2(fmaf(x.z, scl.z, shf.z), fmaf(x.w, scl.w, shf.w));
    ((uint2*)(hb + (size_t)b * SS * CC))[r] = t;
}

// ---------------------------------------------------------------------------
// Flash attention, fp16 m16n8k16 mma. 3-stage cp.async ring, one barrier per
// chunk. P fragments come STRAIGHT from the S accumulator (fp16 layout
// identity) - no shuffles, no smem round-trip. Style dedup (16 chunks for
// self-style batches). Max-free softmax (exp2 space; style bias = +1.0).
// CTA: 128 queries of one (b,h), 8 warps x 16 q-rows, chunks of 64 keys.
// Smem pitch 72 fp16 (144 B). Stage = K(9216) + V(9216) = 18432 B.
// ---------------------------------------------------------------------------
#define AFP 72
#define KS_OFF(s) ((s) * 18432)
#define VS_OFF(s) ((s) * 18432 + 9216)
#define ATT_SMEM  (3 * 18432)    // 55296 bytes

__global__ __launch_bounds__(256, 2) void k_attn_mma()
{
    extern __shared__ __align__(16) uint32_t sm[];
    char* smc = (char*)sm;

    const int tid  = threadIdx.x;
    const int warp = tid >> 5, lane = tid & 31;
    const int tg   = lane & 3, gid = lane >> 2;

    // remap: groups {0,1,2,3} -> batches {1,3,0,2}; long CTAs first
    const int yb = blockIdx.y;
    const int h  = yb % HH;
    const int grp = yb / HH;
    const int b  = (grp == 0) ? 1 : (grp == 1) ? 3 : (grp == 2) ? 0 : 2;

    const int q0   = blockIdx.x * 128;
    const int sbv  = (b < BB / 2) ? 0 : BB / 2;
    const int nch  = (b == sbv) ? 16 : 32;
    const int wq   = warp * 16;

    const uint32_t smb = smem_u32(sm);
    const int frow = tid >> 3, fcol = tid & 7;

    const int lr = lane & 7;
    const uint32_t aoff = ((wq + ((lane >> 3) & 1) * 8 + lr) * AFP
                           + ((lane >> 4) & 1) * 8) * 2;
    const uint32_t kvoff = (((lane >> 4) * 8 + lr) * AFP
                           + ((lane >> 3) & 1) * 8) * 2;

    // ---- stage Q tile (128 x 64 fp16) through stage-0 region, grab frags ----
    {
        const __half* Qg = g_qh + (size_t)(b * SS + q0) * CC + h * DD;
#pragma unroll
        for (int i = 0; i < 4; i++) {
            int fid = tid + i * 256;
            int row = fid >> 3, c8 = fid & 7;
            *(uint4*)(smc + row * 144 + c8 * 16) =
                *(const uint4*)(Qg + (size_t)row * CC + c8 * 8);
        }
    }
    __syncthreads();

    uint32_t qf[4][4];
#pragma unroll
    for (int ks = 0; ks < 4; ks++) LDSM_X4(qf[ks], smb + aoff + ks * 32);
    __syncthreads();   // Q reads done; stage 0 free for chunk 0

    float o[8][4];
#pragma unroll
    for (int n_ = 0; n_ < 8; n_++)
#pragma unroll
        for (int r = 0; r < 4; r++) o[n_][r] = 0.f;
    float l0r = 0.f, l1r = 0.f;

    const __half* Kbase0 = g_kh + (size_t)b * SS * CC + h * DD;
    const __half* Kbase1 = g_kh + (size_t)sbv * SS * CC + h * DD;
    const __half* Vbase0 = g_vth + ((size_t)(b * HH + h) * DD) * SS;
    const __half* Vbase1 = g_vth + ((size_t)(sbv * HH + h) * DD) * SS;

#define AISSUE(c, s) do { \
    const int _self = ((c) < 16); \
    const int _kr   = (_self ? (c) : (c) - 16) * 64; \
    const __half* _Kg = (_self ? Kbase0 : Kbase1) + (size_t)_kr * CC; \
    const __half* _Vg = (_self ? Vbase0 : Vbase1) + _kr; \
    uint32_t _kd = smb + KS_OFF(s) + frow * 144 + fcol * 16; \
    uint32_t _vd = smb + VS_OFF(s) + frow * 144 + fcol * 16; \
    _Pragma("unroll") \
    for (int _i = 0; _i < 2; _i++) { \
        int _row = frow + _i * 32; \
        CP_ASYNC16(_kd + _i * 32 * 144, _Kg + (size_t)_row * CC + fcol * 8); \
        CP_ASYNC16(_vd + _i * 32 * 144, _Vg + (size_t)_row * SS + fcol * 8); \
    } \
} while (0)

    // prologue: chunks 0,1 -> stages 0,1
    AISSUE(0, 0); CP_COMMIT();
    AISSUE(1, 1); CP_COMMIT();

    int st = 0;
    for (int ch = 0; ch < nch; ch++) {
        const float b2 = (ch < 16) ? 0.f : 1.0f;   // log2(e)*ln2 == 1

        CP_WAIT1();
        __syncthreads();   // chunk ch visible; refill target's readers done

        int is_ = st + 2; if (is_ >= 3) is_ -= 3;
        if (ch + 2 < nch) AISSUE(ch + 2, is_);
        CP_COMMIT();

        const uint32_t kbase = smb + KS_OFF(st) + kvoff;
        const uint32_t vbase = smb + VS_OFF(st) + kvoff;

        // ---- S = Q @ K^T (16 x 64 per warp), 4 k16 steps ----
        float sacc[8][4];
#pragma unroll
        for (int n_ = 0; n_ < 8; n_++)
#pragma unroll
            for (int r = 0; r < 4; r++) sacc[n_][r] = 0.f;

#pragma unroll
        for (int ks = 0; ks < 4; ks++) {
            uint32_t bf[4][4];
#pragma unroll
            for (int np = 0; np < 4; np++)
                LDSM_X4(bf[np], kbase + np * 16 * 144 + ks * 32);
#pragma unroll
            for (int np = 0; np < 4; np++) {
                mma_16816(sacc[2*np],     qf[ks], bf[np][0], bf[np][1]);
                mma_16816(sacc[2*np + 1], qf[ks], bf[np][2], bf[np][3]);
            }
        }

        // ---- fused softmax + PV: accumulator layout == fp16 A-fragment ----
#pragma unroll
        for (int j = 0; j < 4; j++) {   // k16 blocks of P
            float e0 = fexp2(fmaf(sacc[2*j][0], SC2, b2));
            float e1 = fexp2(fmaf(sacc[2*j][1], SC2, b2));
            float e2 = fexp2(fmaf(sacc[2*j][2], SC2, b2));
            float e3 = fexp2(fmaf(sacc[2*j][3], SC2, b2));
            float f0 = fexp2(fmaf(sacc[2*j+1][0], SC2, b2));
            float f1 = fexp2(fmaf(sacc[2*j+1][1], SC2, b2));
            float f2 = fexp2(fmaf(sacc[2*j+1][2], SC2, b2));
            float f3 = fexp2(fmaf(sacc[2*j+1][3], SC2, b2));
            l0r += (e0 + e1) + (f0 + f1);
            l1r += (e2 + e3) + (f2 + f3);
            uint32_t pf[4];
            pf[0] = pack_h2(e0, e1);
            pf[1] = pack_h2(e2, e3);
            pf[2] = pack_h2(f0, f1);
            pf[3] = pack_h2(f2, f3);

            uint32_t bf[4][4];
#pragma unroll
            for (int np = 0; np < 4; np++)
                LDSM_X4(bf[np], vbase + np * 16 * 144 + j * 32);
#pragma unroll
            for (int np = 0; np < 4; np++) {
                mma_16816(o[2*np],     pf, bf[np][0], bf[np][1]);
                mma_16816(o[2*np + 1], pf, bf[np][2], bf[np][3]);
            }
        }

        if (++st == 3) st = 0;
    }

    // ---- epilogue: quad-reduce row sums, normalize, store fp16 ----
    l0r += __shfl_xor_sync(0xffffffffu, l0r, 1);
    l0r += __shfl_xor_sync(0xffffffffu, l0r, 2);
    l1r += __shfl_xor_sync(0xffffffffu, l1r, 1);
    l1r += __shfl_xor_sync(0xffffffffu, l1r, 2);
    const float inv0 = 1.0f / l0r, inv1 = 1.0f / l1r;
    __half* Og = g_attnh + (size_t)(b * SS + q0 + wq) * CC + h * DD;
#pragma unroll
    for (int n_ = 0; n_ < 8; n_++) {
        int col = n_ * 8 + tg * 2;
        uint32_t lo = pack_h2(o[n_][0] * inv0, o[n_][1] * inv0);
        uint32_t hi = pack_h2(o[n_][2] * inv1, o[n_][3] * inv1);
        *(uint32_t*)(Og + (size_t)gid * CC + col)       = lo;
        *(uint32_t*)(Og + (size_t)(gid + 8) * CC + col) = hi;
    }
}

// ---------------------------------------------------------------------------
extern "C" void kernel_launch(void* const* d_in, const int* in_sizes, int n_in,
                              void* d_out, int out_size)
{
    (void)in_sizes; (void)n_in; (void)out_size;
    const float* X  = (const float*)d_in[0];
    const float* Wq = (const float*)d_in[1];
    const float* Wk = (const float*)d_in[2];
    const float* Wv = (const float*)d_in[3];
    const float* Wo = (const float*)d_in[4];
    const float* bo = (const float*)d_in[5];
    float* out = (float*)d_out;

    cudaFuncSetAttribute(k_attn_mma, cudaFuncAttributeMaxDynamicSharedMemorySize,
                         ATT_SMEM);
    cudaFuncSetAttribute(k_qkv_mma, cudaFuncAttributeMaxDynamicSharedMemorySize,
                         GEMM_SMEM);
    cudaFuncSetAttribute(k_proj_mma, cudaFuncAttributeMaxDynamicSharedMemorySize,
                         GEMM_SMEM);

    k_cvt<<<(CVT_F4 + 255) / 256, 256>>>(X, Wq, Wk, Wv, Wo);
    k_qkv_mma<<<dim3(CC / 128, (BB * SS) / 128, 3), 256, GEMM_SMEM>>>();
    k_transv<<<dim3(SS / 32, DD / 32, BB * HH), dim3(32, 8)>>>();
    k_stats<<<dim3(CC / 128, BB, 32), 128>>>();
    k_finalize<<<(2 * BB * CC + 255) / 256, 256>>>();
    k_apply<<<(2 * BB * SS * CC / 4 + 255) / 256, 256>>>();
    k_attn_mma<<<dim3(SS / 128, BB * HH), 256, ATT_SMEM>>>();
    k_proj_mma<<<dim3(CC / 128, (BB * SS) / 128), 256, GEMM_SMEM>>>(bo, out);
}

// round 14
// speedup vs baseline: 1.9048x; 1.0002x over previous
#include <cuda_runtime.h>
#include <cuda_fp16.h>
#include <cstdint>
#include <math.h>

// Problem constants
#define BB 4
#define SS 1024
#define CC 1280
#define HH 20
#define DD 64
#define SC2 0.18033688011112042f      // 64^-0.5 * log2(e)
#define EPSV 1e-5f

// ---------------- scratch (static device allocations are allowed) -----------
#define XN (BB*SS*CC)     // 5242880
#define WN (CC*CC)        // 1638400
__device__ __align__(16) __half g_xh[XN + 4*WN];   // fp16 [X | Wq | Wk | Wv | Wo]
__device__ float  g_q[BB*SS*CC];                   // fp32 Q (pre-AdaIN)
__device__ float  g_k[BB*SS*CC];                   // fp32 K
__device__ __align__(16) __half g_qh[BB*SS*CC];    // fp16 AdaIN'd Q
__device__ __align__(16) __half g_kh[BB*SS*CC];    // fp16 AdaIN'd K
__device__ __align__(16) __half g_vh[BB*SS*CC];    // fp16 V (from GEMM)
__device__ __align__(16) __half g_vth[BB*SS*CC];   // fp16 V transposed [b][h][d][s]
__device__ __align__(16) __half g_attnh[BB*SS*CC]; // fp16 attention output
__device__ float  g_psum[2*BB*16*CC];
__device__ float  g_psq [2*BB*16*CC];
__device__ float  g_scl[2*BB*CC];
__device__ float  g_shf[2*BB*CC];
__device__ int    g_ctr;                           // attention work-queue counter

// =================== helpers (sm_75+/sm_80+ PTX, base-target safe) =========
__device__ __forceinline__ float fexp2(float x) {
    float y;
    asm("ex2.approx.f32 %0, %1;" : "=f"(y) : "f"(x));
    return y;
}

__device__ __forceinline__ void mma_16816(
    float c[4], const uint32_t a[4], uint32_t b0, uint32_t b1)
{
    asm volatile(
        "mma.sync.aligned.m16n8k16.row.col.f32.f16.f16.f32 "
        "{%0,%1,%2,%3}, {%4,%5,%6,%7}, {%8,%9}, {%0,%1,%2,%3};\n"
        : "+f"(c[0]), "+f"(c[1]), "+f"(c[2]), "+f"(c[3])
        : "r"(a[0]), "r"(a[1]), "r"(a[2]), "r"(a[3]), "r"(b0), "r"(b1));
}

__device__ __forceinline__ uint32_t smem_u32(const void* p) {
    uint32_t a;
    asm("{ .reg .u64 t; cvta.to.shared.u64 t, %1; cvt.u32.u64 %0, t; }"
        : "=r"(a) : "l"(p));
    return a;
}

__device__ __forceinline__ uint32_t pack_h2(float a, float b) {
    __half2 t = __floats2half2_rn(a, b);
    return *(uint32_t*)&t;
}

#define LDSM_X4(R, addr) \
    asm volatile("ldmatrix.sync.aligned.m8n8.x4.shared.b16 {%0,%1,%2,%3}, [%4];" \
        : "=r"((R)[0]), "=r"((R)[1]), "=r"((R)[2]), "=r"((R)[3]) : "r"(addr))

#define CP_ASYNC16(dst, src) \
    asm volatile("cp.async.cg.shared.global [%0], [%1], 16;" \
        :: "r"(dst), "l"(src))
#define CP_COMMIT() asm volatile("cp.async.commit_group;")
#define CP_WAIT1()  asm volatile("cp.async.wait_group 1;")

// ---------------------------------------------------------------------------
// fp16 conversion pass over [X | Wq | Wk | Wv | Wo] + work-queue reset
// ---------------------------------------------------------------------------
#define CVT_F4 ((XN + 4*WN) / 4)
__global__ __launch_bounds__(256) void k_cvt(
    const float* __restrict__ X,  const float* __restrict__ Wq,
    const float* __restrict__ Wk, const float* __restrict__ Wv,
    const float* __restrict__ Wo)
{
    if (blockIdx.x == 0 && threadIdx.x == 0) g_ctr = 0;
    int i4 = blockIdx.x * 256 + threadIdx.x;
    if (i4 >= CVT_F4) return;
    const float* src;
    int base;
    if      (i4 < XN/4)          { src = X;  base = 0; }
    else if (i4 < (XN+WN)/4)     { src = Wq; base = XN/4; }
    else if (i4 < (XN+2*WN)/4)   { src = Wk; base = (XN+WN)/4; }
    else if (i4 < (XN+3*WN)/4)   { src = Wv; base = (XN+2*WN)/4; }
    else                         { src = Wo; base = (XN+3*WN)/4; }
    float4 v = ((const float4*)src)[i4 - base];
    uint2 t;
    t.x = pack_h2(v.x, v.y);
    t.y = pack_h2(v.z, v.w);
    ((uint2*)g_xh)[i4] = t;
}

// ---------------------------------------------------------------------------
// Tensor-core fp16 GEMM (fp32 accum): C = A @ W^T (+bias). Inputs fp16.
// Block 128x128, BK=32 fp16, 3-stage cp.async, one barrier per k-tile.
// Epilogue writes fp32 (CoutF) or fp16 (CoutH).
// ---------------------------------------------------------------------------
#define GKT (CC / 32)   // 40 k-tiles
#define GST 10240
#define GBOFF 30720
#define GEMM_SMEM 61440

#define GISSUE(t, s) do { \
    uint32_t _da = base + (s) * GST + stoff; \
    uint32_t _db = base + GBOFF + (s) * GST + stoff; \
    const __half* _An = Ap + (t) * 32; \
    const __half* _Bn = Bp + (t) * 32; \
    CP_ASYNC16(_da,      _An); \
    CP_ASYNC16(_da + 16, _An + 8); \
    CP_ASYNC16(_db,      _Bn); \
    CP_ASYNC16(_db + 16, _Bn + 8); \
} while (0)

__device__ __forceinline__ void gemm_mma_body(
    const __half* __restrict__ A, const __half* __restrict__ W,
    const float* __restrict__ bias, float* __restrict__ CoutF,
    __half* __restrict__ CoutH)
{
    extern __shared__ __align__(16) uint32_t gsm[];

    const int tid  = threadIdx.x;
    const int warp = tid >> 5, lane = tid & 31;
    const int wm   = (warp & 3) * 32;
    const int wn   = (warp >> 2) * 64;
    const int tg   = lane & 3, gid = lane >> 2;
    const int m0   = blockIdx.y * 128;
    const int n0   = blockIdx.x * 128;

    const int lrow = tid >> 1;
    const int lc   = (tid & 1) * 16;
    const __half* Ap = A + (size_t)(m0 + lrow) * CC + lc;
    const __half* Bp = W + (size_t)(n0 + lrow) * CC + lc;

    const uint32_t base  = smem_u32(gsm);
    const uint32_t stoff = (uint32_t)(lrow * 40 + lc) * 2;

    const int lr = lane & 7;
    const uint32_t aoff = ((wm + ((lane >> 3) & 1) * 8 + lr) * 40
                           + ((lane >> 4) & 1) * 8) * 2;
    const uint32_t boff = ((wn + (lane >> 4) * 8 + lr) * 40
                           + ((lane >> 3) & 1) * 8) * 2;

    float acc[2][8][4];
#pragma unroll
    for (int im = 0; im < 2; im++)
#pragma unroll
        for (int in_ = 0; in_ < 8; in_++)
#pragma unroll
            for (int r = 0; r < 4; r++) acc[im][in_][r] = 0.f;

    GISSUE(0, 0); CP_COMMIT();
    GISSUE(1, 1); CP_COMMIT();

    int cs = 0;
    for (int kt = 0; kt < GKT; kt++) {
        CP_WAIT1();
        __syncthreads();

        int is_ = cs + 2; if (is_ >= 3) is_ -= 3;
        if (kt + 2 < GKT) GISSUE(kt + 2, is_);
        CP_COMMIT();

        const uint32_t sal = base + cs * GST + aoff;
        const uint32_t sbl = base + GBOFF + cs * GST + boff;
#pragma unroll
        for (int ks = 0; ks < 2; ks++) {
            uint32_t af[2][4];
            uint32_t bf[4][4];
            LDSM_X4(af[0], sal + ks * 32);
            LDSM_X4(af[1], sal + 16 * 80 + ks * 32);
#pragma unroll
            for (int np = 0; np < 4; np++)
                LDSM_X4(bf[np], sbl + np * 16 * 80 + ks * 32);
#pragma unroll
            for (int np = 0; np < 4; np++) {
                mma_16816(acc[0][2*np],     af[0], bf[np][0], bf[np][1]);
                mma_16816(acc[0][2*np + 1], af[0], bf[np][2], bf[np][3]);
                mma_16816(acc[1][2*np],     af[1], bf[np][0], bf[np][1]);
                mma_16816(acc[1][2*np + 1], af[1], bf[np][2], bf[np][3]);
            }
        }
        if (++cs == 3) cs = 0;
    }

#pragma unroll
    for (int im = 0; im < 2; im++) {
        int row = m0 + wm + im * 16 + gid;
#pragma unroll
        for (int in_ = 0; in_ < 8; in_++) {
            int col = n0 + wn + in_ * 8 + tg * 2;
            if (CoutH) {
                uint32_t lo = pack_h2(acc[im][in_][0], acc[im][in_][1]);
                uint32_t hi = pack_h2(acc[im][in_][2], acc[im][in_][3]);
                *(uint32_t*)(CoutH + (size_t)row * CC + col)       = lo;
                *(uint32_t*)(CoutH + (size_t)(row + 8) * CC + col) = hi;
            } else {
                float b0v = 0.f, b1v = 0.f;
                if (bias) { b0v = bias[col]; b1v = bias[col + 1]; }
                float2 lo = make_float2(acc[im][in_][0] + b0v, acc[im][in_][1] + b1v);
                float2 hi = make_float2(acc[im][in_][2] + b0v, acc[im][in_][3] + b1v);
                *(float2*)(CoutF + (size_t)row * CC + col)       = lo;
                *(float2*)(CoutF + (size_t)(row + 8) * CC + col) = hi;
            }
        }
    }
}

__global__ __launch_bounds__(256) void k_qkv_mma()
{
    const __half* X = g_xh;
    const __half* W = g_xh + XN + (size_t)blockIdx.z * WN;
    if (blockIdx.z == 0)      gemm_mma_body(X, W, nullptr, g_q, nullptr);
    else if (blockIdx.z == 1) gemm_mma_body(X, W, nullptr, g_k, nullptr);
    else                      gemm_mma_body(X, W, nullptr, nullptr, g_vh);
}

__global__ __launch_bounds__(256) void k_proj_mma(
    const float* __restrict__ bo, float* __restrict__ out)
{
    gemm_mma_body(g_attnh, g_xh + XN + 3 * (size_t)WN, bo, out, nullptr);
}

// ---------------------------------------------------------------------------
// V transpose: g_vh [b][s][h][d] fp16 -> g_vth [b][h][d][s] fp16
// ---------------------------------------------------------------------------
__global__ __launch_bounds__(256) void k_transv()
{
    __shared__ __half tile[32][33];
    const int bh = blockIdx.z;
    const int b  = bh / HH, h = bh % HH;
    const int s0 = blockIdx.x * 32;
    const int d0 = blockIdx.y * 32;
    const int tx = threadIdx.x, ty = threadIdx.y;

    const __half* src = g_vh + (size_t)(b * SS + s0) * CC + h * DD + d0;
#pragma unroll
    for (int j = 0; j < 32; j += 8)
        tile[ty + j][tx] = src[(size_t)(ty + j) * CC + tx];
    __syncthreads();

    __half* dst = g_vth + ((size_t)(b * HH + h) * DD + d0) * SS + s0;
#pragma unroll
    for (int j = 0; j < 32; j += 8)
        dst[(size_t)(ty + j) * SS + tx] = tile[tx][ty + j];
}

// ---------------------------------------------------------------------------
// AdaIN stats (split-S, 16 segments, fp32 Q/K) / finalize / apply (fp16 out)
// ---------------------------------------------------------------------------
__global__ void k_stats()
{
    const int c   = blockIdx.x * 128 + threadIdx.x;
    const int b   = blockIdx.y;
    const int z   = blockIdx.z >> 4;
    const int seg = blockIdx.z & 15;
    const float* src = z ? g_k : g_q;
    const float* p = src + ((size_t)b * SS + seg * 64) * CC + c;

    float s0 = 0, s1 = 0, q0 = 0, q1 = 0;
#pragma unroll 4
    for (int s = 0; s < 64; s += 2) {
        float x0 = p[(size_t)(s + 0) * CC];
        float x1 = p[(size_t)(s + 1) * CC];
        s0 += x0; q0 = fmaf(x0, x0, q0);
        s1 += x1; q1 = fmaf(x1, x1, q1);
    }
    int idx = ((z * BB + b) * 16 + seg) * CC + c;
    g_psum[idx] = s0 + s1;
    g_psq [idx] = q0 + q1;
}

__global__ void k_finalize()
{
    int i = blockIdx.x * 256 + threadIdx.x;
    if (i >= 2 * BB * CC) return;
    int c  = i % CC;
    int b  = (i / CC) % BB;
    int z  = i / (CC * BB);
    int sb = (b < BB / 2) ? 0 : BB / 2;

    float sum = 0, sq = 0, sums = 0, sqs = 0;
#pragma unroll
    for (int seg = 0; seg < 16; seg++) {
        sum  += g_psum[((z * BB + b)  * 16 + seg) * CC + c];
        sq   += g_psq [((z * BB + b)  * 16 + seg) * CC + c];
        sums += g_psum[((z * BB + sb) * 16 + seg) * CC + c];
        sqs  += g_psq [((z * BB + sb) * 16 + seg) * CC + c];
    }
    float mean  = sum  * (1.0f / SS);
    float means = sums * (1.0f / SS);
    float sd  = sqrtf((sq  - sum  * mean ) * (1.0f / (SS - 1)) + EPSV);
    float sds = sqrtf((sqs - sums * means) * (1.0f / (SS - 1)) + EPSV);
    float scl = sds / sd;
    g_scl[i] = scl;
    g_shf[i] = means - mean * scl;
}

__global__ void k_apply()
{
    const int TOT4  = 2 * BB * SS * CC / 4;
    const int per_t = SS * CC / 4;
    int i4 = blockIdx.x * 256 + threadIdx.x;
    if (i4 >= TOT4) return;
    int zb = i4 / per_t;
    int r  = i4 % per_t;
    int c  = (r % (CC / 4)) * 4;
    const float* fb = (zb < BB) ? g_q : g_k;
    __half*      hb = (zb < BB) ? g_qh : g_kh;
    int b = zb & 3;
    float4 x = ((const float4*)(fb + (size_t)b * SS * CC))[r];
    float4 scl = *(const float4*)&g_scl[zb * CC + c];
    float4 shf = *(const float4*)&g_shf[zb * CC + c];
    uint2 t;
    t.x = pack_h2(fmaf(x.x, scl.x, shf.x), fmaf(x.y, scl.y, shf.y));
    t.y = pack_h2(fmaf(x.z, scl.z, shf.z), fmaf(x.w, scl.w, shf.w));
    ((uint2*)(hb + (size_t)b * SS * CC))[r] = t;
}

// ---------------------------------------------------------------------------
// Flash attention, fp16 m16n8k16 mma, PERSISTENT CTAs + atomic work queue
// (longest items first => near-ideal load balance). 3-stage cp.async ring,
// one barrier per chunk, P straight from S accumulator, style dedup,
// max-free softmax. Item = (b, h, 128-query block); long items (b=1,3)
// run 32 chunks, short (b=0,2) 16.
// ---------------------------------------------------------------------------
#define AFP 72
#define KS_OFF(s) ((s) * 18432)
#define VS_OFF(s) ((s) * 18432 + 9216)
#define ATT_SMEM  (3 * 18432)    // 55296 bytes
#define N_ITEMS 640

__global__ __launch_bounds__(256, 2) void k_attn_mma()
{
    extern __shared__ __align__(16) uint32_t sm[];
    __shared__ int s_item;
    char* smc = (char*)sm;

    const int tid  = threadIdx.x;
    const int warp = tid >> 5, lane = tid & 31;
    const int tg   = lane & 3, gid = lane >> 2;
    const int wq   = warp * 16;

    const uint32_t smb = smem_u32(sm);
    const int frow = tid >> 3, fcol = tid & 7;

    const int lr = lane & 7;
    const uint32_t aoff = ((wq + ((lane >> 3) & 1) * 8 + lr) * AFP
                           + ((lane >> 4) & 1) * 8) * 2;
    const uint32_t kvoff = (((lane >> 4) * 8 + lr) * AFP
                           + ((lane >> 3) & 1) * 8) * 2;

    while (true) {
        if (tid == 0) s_item = atomicAdd(&g_ctr, 1);
        __syncthreads();                 // broadcast item; prior item fully done
        const int item = s_item;
        if (item >= N_ITEMS) break;

        // decode: items 0..319 long (b=1,3), 320..639 short (b=0,2)
        int b, rem;
        if (item < 320) { b = 1 + 2 * (item / 160); rem = item % 160; }
        else            { int j = item - 320; b = 2 * (j / 160); rem = j % 160; }
        const int h  = rem / 8;
        const int q0 = (rem % 8) * 128;
        const int sbv = (b < BB / 2) ? 0 : BB / 2;
        const int nch = (b == sbv) ? 16 : 32;

        // ---- stage Q tile (128x64 fp16) through stage-0, grab frags ----
        {
            const __half* Qg = g_qh + (size_t)(b * SS + q0) * CC + h * DD;
#pragma unroll
            for (int i = 0; i < 4; i++) {
                int fid = tid + i * 256;
                int row = fid >> 3, c8 = fid & 7;
                *(uint4*)(smc + row * 144 + c8 * 16) =
                    *(const uint4*)(Qg + (size_t)row * CC + c8 * 8);
            }
        }
        __syncthreads();

        uint32_t qf[4][4];
#pragma unroll
        for (int ks = 0; ks < 4; ks++) LDSM_X4(qf[ks], smb + aoff + ks * 32);
        __syncthreads();   // Q reads done; stage 0 free for chunk 0

        float o[8][4];
#pragma unroll
        for (int n_ = 0; n_ < 8; n_++)
#pragma unroll
            for (int r = 0; r < 4; r++) o[n_][r] = 0.f;
        float l0r = 0.f, l1r = 0.f;

        const __half* Kbase0 = g_kh + (size_t)b * SS * CC + h * DD;
        const __half* Kbase1 = g_kh + (size_t)sbv * SS * CC + h * DD;
        const __half* Vbase0 = g_vth + ((size_t)(b * HH + h) * DD) * SS;
        const __half* Vbase1 = g_vth + ((size_t)(sbv * HH + h) * DD) * SS;

#define AISSUE(c, s) do { \
    const int _self = ((c) < 16); \
    const int _kr   = (_self ? (c) : (c) - 16) * 64; \
    const __half* _Kg = (_self ? Kbase0 : Kbase1) + (size_t)_kr * CC; \
    const __half* _Vg = (_self ? Vbase0 : Vbase1) + _kr; \
    uint32_t _kd = smb + KS_OFF(s) + frow * 144 + fcol * 16; \
    uint32_t _vd = smb + VS_OFF(s) + frow * 144 + fcol * 16; \
    _Pragma("unroll") \
    for (int _i = 0; _i < 2; _i++) { \
        int _row = frow + _i * 32; \
        CP_ASYNC16(_kd + _i * 32 * 144, _Kg + (size_t)_row * CC + fcol * 8); \
        CP_ASYNC16(_vd + _i * 32 * 144, _Vg + (size_t)_row * SS + fcol * 8); \
    } \
} while (0)

        AISSUE(0, 0); CP_COMMIT();
        AISSUE(1, 1); CP_COMMIT();

        int st = 0;
        for (int ch = 0; ch < nch; ch++) {
            const float b2 = (ch < 16) ? 0.f : 1.0f;   // log2(e)*ln2 == 1

            CP_WAIT1();
            __syncthreads();

            int is_ = st + 2; if (is_ >= 3) is_ -= 3;
            if (ch + 2 < nch) AISSUE(ch + 2, is_);
            CP_COMMIT();

            const uint32_t kbase = smb + KS_OFF(st) + kvoff;
            const uint32_t vbase = smb + VS_OFF(st) + kvoff;

            // ---- S = Q @ K^T (16 x 64 per warp), 4 k16 steps ----
            float sacc[8][4];
#pragma unroll
            for (int n_ = 0; n_ < 8; n_++)
#pragma unroll
                for (int r = 0; r < 4; r++) sacc[n_][r] = 0.f;

#pragma unroll
            for (int ks = 0; ks < 4; ks++) {
                uint32_t bf[4][4];
#pragma unroll
                for (int np = 0; np < 4; np++)
                    LDSM_X4(bf[np], kbase + np * 16 * 144 + ks * 32);
#pragma unroll
                for (int np = 0; np < 4; np++) {
                    mma_16816(sacc[2*np],     qf[ks], bf[np][0], bf[np][1]);
                    mma_16816(sacc[2*np + 1], qf[ks], bf[np][2], bf[np][3]);
                }
            }

            // ---- fused softmax + PV (accumulator == fp16 A-fragment) ----
#pragma unroll
            for (int j = 0; j < 4; j++) {
                float e0 = fexp2(fmaf(sacc[2*j][0], SC2, b2));
                float e1 = fexp2(fmaf(sacc[2*j][1], SC2, b2));
                float e2 = fexp2(fmaf(sacc[2*j][2], SC2, b2));
                float e3 = fexp2(fmaf(sacc[2*j][3], SC2, b2));
                float f0 = fexp2(fmaf(sacc[2*j+1][0], SC2, b2));
                float f1 = fexp2(fmaf(sacc[2*j+1][1], SC2, b2));
                float f2 = fexp2(fmaf(sacc[2*j+1][2], SC2, b2));
                float f3 = fexp2(fmaf(sacc[2*j+1][3], SC2, b2));
                l0r += (e0 + e1) + (f0 + f1);
                l1r += (e2 + e3) + (f2 + f3);
                uint32_t pf[4];
                pf[0] = pack_h2(e0, e1);
                pf[1] = pack_h2(e2, e3);
                pf[2] = pack_h2(f0, f1);
                pf[3] = pack_h2(f2, f3);

                uint32_t bf[4][4];
#pragma unroll
                for (int np = 0; np < 4; np++)
                    LDSM_X4(bf[np], vbase + np * 16 * 144 + j * 32);
#pragma unroll
                for (int np = 0; np < 4; np++) {
                    mma_16816(o[2*np],     pf, bf[np][0], bf[np][1]);
                    mma_16816(o[2*np + 1], pf, bf[np][2], bf[np][3]);
                }
            }

            if (++st == 3) st = 0;
        }

        // ---- epilogue: quad-reduce row sums, normalize, store fp16 ----
        l0r += __shfl_xor_sync(0xffffffffu, l0r, 1);
        l0r += __shfl_xor_sync(0xffffffffu, l0r, 2);
        l1r += __shfl_xor_sync(0xffffffffu, l1r, 1);
        l1r += __shfl_xor_sync(0xffffffffu, l1r, 2);
        const float inv0 = 1.0f / l0r, inv1 = 1.0f / l1r;
        __half* Og = g_attnh + (size_t)(b * SS + q0 + wq) * CC + h * DD;
#pragma unroll
        for (int n_ = 0; n_ < 8; n_++) {
            int col = n_ * 8 + tg * 2;
            uint32_t lo = pack_h2(o[n_][0] * inv0, o[n_][1] * inv0);
            uint32_t hi = pack_h2(o[n_][2] * inv1, o[n_][3] * inv1);
            *(uint32_t*)(Og + (size_t)gid * CC + col)       = lo;
            *(uint32_t*)(Og + (size_t)(gid + 8) * CC + col) = hi;
        }
    }
}

// ---------------------------------------------------------------------------
extern "C" void kernel_launch(void* const* d_in, const int* in_sizes, int n_in,
                              void* d_out, int out_size)
{
    (void)in_sizes; (void)n_in; (void)out_size;
    const float* X  = (const float*)d_in[0];
    const float* Wq = (const float*)d_in[1];
    const float* Wk = (const float*)d_in[2];
    const float* Wv = (const float*)d_in[3];
    const float* Wo = (const float*)d_in[4];
    const float* bo = (const float*)d_in[5];
    float* out = (float*)d_out;

    cudaFuncSetAttribute(k_attn_mma, cudaFuncAttributeMaxDynamicSharedMemorySize,
                         ATT_SMEM);
    cudaFuncSetAttribute(k_qkv_mma, cudaFuncAttributeMaxDynamicSharedMemorySize,
                         GEMM_SMEM);
    cudaFuncSetAttribute(k_proj_mma, cudaFuncAttributeMaxDynamicSharedMemorySize,
                         GEMM_SMEM);

    k_cvt<<<(CVT_F4 + 255) / 256, 256>>>(X, Wq, Wk, Wv, Wo);
    k_qkv_mma<<<dim3(CC / 128, (BB * SS) / 128, 3), 256, GEMM_SMEM>>>();
    k_transv<<<dim3(SS / 32, DD / 32, BB * HH), dim3(32, 8)>>>();
    k_stats<<<dim3(CC / 128, BB, 32), 128>>>();
    k_finalize<<<(2 * BB * CC + 255) / 256, 256>>>();
    k_apply<<<(2 * BB * SS * CC / 4 + 255) / 256, 256>>>();
    k_attn_mma<<<304, 256, ATT_SMEM>>>();
    k_proj_mma<<<dim3(CC / 128, (BB * SS) / 128), 256, GEMM_SMEM>>>(bo, out);
}

// round 15
// speedup vs baseline: 1.9644x; 1.0313x over previous
#include <cuda_runtime.h>
#include <cuda_fp16.h>
#include <cstdint>
#include <math.h>

// Problem constants
#define BB 4
#define SS 1024
#define CC 1280
#define HH 20
#define DD 64
#define SC2 0.18033688011112042f      // 64^-0.5 * log2(e)
#define EPSV 1e-5f

// ---------------- scratch (static device allocations are allowed) -----------
#define XN (BB*SS*CC)     // 5242880
#define WN (CC*CC)        // 1638400
__device__ __align__(16) __half g_xh[XN + 4*WN];   // fp16 [X | Wq | Wk | Wv | Wo]
__device__ __align__(16) __half g_qp[BB*SS*CC];    // fp16 Q (pre-AdaIN)
__device__ __align__(16) __half g_kp[BB*SS*CC];    // fp16 K (pre-AdaIN)
__device__ __align__(16) __half g_qh[BB*SS*CC];    // fp16 AdaIN'd Q
__device__ __align__(16) __half g_kh[BB*SS*CC];    // fp16 AdaIN'd K
__device__ __align__(16) __half g_vh[BB*SS*CC];    // fp16 V (from GEMM)
__device__ __align__(16) __half g_attnh[BB*SS*CC]; // fp16 attention output
__device__ float  g_psum[2*BB*16*CC];
__device__ float  g_psq [2*BB*16*CC];
__device__ float  g_scl[2*BB*CC];
__device__ float  g_shf[2*BB*CC];
__device__ int    g_ctr;                           // attention work-queue counter

// =================== helpers (sm_75+/sm_80+ PTX, base-target safe) =========
__device__ __forceinline__ float fexp2(float x) {
    float y;
    asm("ex2.approx.f32 %0, %1;" : "=f"(y) : "f"(x));
    return y;
}

__device__ __forceinline__ void mma_16816(
    float c[4], const uint32_t a[4], uint32_t b0, uint32_t b1)
{
    asm volatile(
        "mma.sync.aligned.m16n8k16.row.col.f32.f16.f16.f32 "
        "{%0,%1,%2,%3}, {%4,%5,%6,%7}, {%8,%9}, {%0,%1,%2,%3};\n"
        : "+f"(c[0]), "+f"(c[1]), "+f"(c[2]), "+f"(c[3])
        : "r"(a[0]), "r"(a[1]), "r"(a[2]), "r"(a[3]), "r"(b0), "r"(b1));
}

__device__ __forceinline__ uint32_t smem_u32(const void* p) {
    uint32_t a;
    asm("{ .reg .u64 t; cvta.to.shared.u64 t, %1; cvt.u32.u64 %0, t; }"
        : "=r"(a) : "l"(p));
    return a;
}

__device__ __forceinline__ uint32_t pack_h2(float a, float b) {
    __half2 t = __floats2half2_rn(a, b);
    return *(uint32_t*)&t;
}

#define LDSM_X4(R, addr) \
    asm volatile("ldmatrix.sync.aligned.m8n8.x4.shared.b16 {%0,%1,%2,%3}, [%4];" \
        : "=r"((R)[0]), "=r"((R)[1]), "=r"((R)[2]), "=r"((R)[3]) : "r"(addr))

#define LDSM_X4T(R, addr) \
    asm volatile("ldmatrix.sync.aligned.m8n8.x4.trans.shared.b16 {%0,%1,%2,%3}, [%4];" \
        : "=r"((R)[0]), "=r"((R)[1]), "=r"((R)[2]), "=r"((R)[3]) : "r"(addr))

#define CP_ASYNC16(dst, src) \
    asm volatile("cp.async.cg.shared.global [%0], [%1], 16;" \
        :: "r"(dst), "l"(src))
#define CP_COMMIT() asm volatile("cp.async.commit_group;")
#define CP_WAIT1()  asm volatile("cp.async.wait_group 1;")

// ---------------------------------------------------------------------------
// fp16 conversion pass over [X | Wq | Wk | Wv | Wo] + work-queue reset
// ---------------------------------------------------------------------------
#define CVT_F4 ((XN + 4*WN) / 4)
__global__ __launch_bounds__(256) void k_cvt(
    const float* __restrict__ X,  const float* __restrict__ Wq,
    const float* __restrict__ Wk, const float* __restrict__ Wv,
    const float* __restrict__ Wo)
{
    if (blockIdx.x == 0 && threadIdx.x == 0) g_ctr = 0;
    int i4 = blockIdx.x * 256 + threadIdx.x;
    if (i4 >= CVT_F4) return;
    const float* src;
    int base;
    if      (i4 < XN/4)          { src = X;  base = 0; }
    else if (i4 < (XN+WN)/4)     { src = Wq; base = XN/4; }
    else if (i4 < (XN+2*WN)/4)   { src = Wk; base = (XN+WN)/4; }
    else if (i4 < (XN+3*WN)/4)   { src = Wv; base = (XN+2*WN)/4; }
    else                         { src = Wo; base = (XN+3*WN)/4; }
    float4 v = ((const float4*)src)[i4 - base];
    uint2 t;
    t.x = pack_h2(v.x, v.y);
    t.y = pack_h2(v.z, v.w);
    ((uint2*)g_xh)[i4] = t;
}

// ---------------------------------------------------------------------------
// Tensor-core fp16 GEMM (fp32 accum): C = A @ W^T (+bias). Inputs fp16.
// Block 128x128, BK=32 fp16, 3-stage cp.async, one barrier per k-tile.
// Epilogue writes fp32 (CoutF) or fp16 (CoutH).
// ---------------------------------------------------------------------------
#define GKT (CC / 32)   // 40 k-tiles
#define GST 10240
#define GBOFF 30720
#define GEMM_SMEM 61440

#define GISSUE(t, s) do { \
    uint32_t _da = base + (s) * GST + stoff; \
    uint32_t _db = base + GBOFF + (s) * GST + stoff; \
    const __half* _An = Ap + (t) * 32; \
    const __half* _Bn = Bp + (t) * 32; \
    CP_ASYNC16(_da,      _An); \
    CP_ASYNC16(_da + 16, _An + 8); \
    CP_ASYNC16(_db,      _Bn); \
    CP_ASYNC16(_db + 16, _Bn + 8); \
} while (0)

__device__ __forceinline__ void gemm_mma_body(
    const __half* __restrict__ A, const __half* __restrict__ W,
    const float* __restrict__ bias, float* __restrict__ CoutF,
    __half* __restrict__ CoutH)
{
    extern __shared__ __align__(16) uint32_t gsm[];

    const int tid  = threadIdx.x;
    const int warp = tid >> 5, lane = tid & 31;
    const int wm   = (warp & 3) * 32;
    const int wn   = (warp >> 2) * 64;
    const int tg   = lane & 3, gid = lane >> 2;
    const int m0   = blockIdx.y * 128;
    const int n0   = blockIdx.x * 128;

    const int lrow = tid >> 1;
    const int lc   = (tid & 1) * 16;
    const __half* Ap = A + (size_t)(m0 + lrow) * CC + lc;
    const __half* Bp = W + (size_t)(n0 + lrow) * CC + lc;

    const uint32_t base  = smem_u32(gsm);
    const uint32_t stoff = (uint32_t)(lrow * 40 + lc) * 2;

    const int lr = lane & 7;
    const uint32_t aoff = ((wm + ((lane >> 3) & 1) * 8 + lr) * 40
                           + ((lane >> 4) & 1) * 8) * 2;
    const uint32_t boff = ((wn + (lane >> 4) * 8 + lr) * 40
                           + ((lane >> 3) & 1) * 8) * 2;

    float acc[2][8][4];
#pragma unroll
    for (int im = 0; im < 2; im++)
#pragma unroll
        for (int in_ = 0; in_ < 8; in_++)
#pragma unroll
            for (int r = 0; r < 4; r++) acc[im][in_][r] = 0.f;

    GISSUE(0, 0); CP_COMMIT();
    GISSUE(1, 1); CP_COMMIT();

    int cs = 0;
    for (int kt = 0; kt < GKT; kt++) {
        CP_WAIT1();
        __syncthreads();

        int is_ = cs + 2; if (is_ >= 3) is_ -= 3;
        if (kt + 2 < GKT) GISSUE(kt + 2, is_);
        CP_COMMIT();

        const uint32_t sal = base + cs * GST + aoff;
        const uint32_t sbl = base + GBOFF + cs * GST + boff;
#pragma unroll
        for (int ks = 0; ks < 2; ks++) {
            uint32_t af[2][4];
            uint32_t bf[4][4];
            LDSM_X4(af[0], sal + ks * 32);
            LDSM_X4(af[1], sal + 16 * 80 + ks * 32);
#pragma unroll
            for (int np = 0; np < 4; np++)
                LDSM_X4(bf[np], sbl + np * 16 * 80 + ks * 32);
#pragma unroll
            for (int np = 0; np < 4; np++) {
                mma_16816(acc[0][2*np],     af[0], bf[np][0], bf[np][1]);
                mma_16816(acc[0][2*np + 1], af[0], bf[np][2], bf[np][3]);
                mma_16816(acc[1][2*np],     af[1], bf[np][0], bf[np][1]);
                mma_16816(acc[1][2*np + 1], af[1], bf[np][2], bf[np][3]);
            }
        }
        if (++cs == 3) cs = 0;
    }

#pragma unroll
    for (int im = 0; im < 2; im++) {
        int row = m0 + wm + im * 16 + gid;
#pragma unroll
        for (int in_ = 0; in_ < 8; in_++) {
            int col = n0 + wn + in_ * 8 + tg * 2;
            if (CoutH) {
                uint32_t lo = pack_h2(acc[im][in_][0], acc[im][in_][1]);
                uint32_t hi = pack_h2(acc[im][in_][2], acc[im][in_][3]);
                *(uint32_t*)(CoutH + (size_t)row * CC + col)       = lo;
                *(uint32_t*)(CoutH + (size_t)(row + 8) * CC + col) = hi;
            } else {
                float b0v = 0.f, b1v = 0.f;
                if (bias) { b0v = bias[col]; b1v = bias[col + 1]; }
                float2 lo = make_float2(acc[im][in_][0] + b0v, acc[im][in_][1] + b1v);
                float2 hi = make_float2(acc[im][in_][2] + b0v, acc[im][in_][3] + b1v);
                *(float2*)(CoutF + (size_t)row * CC + col)       = lo;
                *(float2*)(CoutF + (size_t)(row + 8) * CC + col) = hi;
            }
        }
    }
}

__global__ __launch_bounds__(256) void k_qkv_mma()
{
    const __half* X = g_xh;
    const __half* W = g_xh + XN + (size_t)blockIdx.z * WN;
    if (blockIdx.z == 0)      gemm_mma_body(X, W, nullptr, nullptr, g_qp);
    else if (blockIdx.z == 1) gemm_mma_body(X, W, nullptr, nullptr, g_kp);
    else                      gemm_mma_body(X, W, nullptr, nullptr, g_vh);
}

__global__ __launch_bounds__(256) void k_proj_mma(
    const float* __restrict__ bo, float* __restrict__ out)
{
    gemm_mma_body(g_attnh, g_xh + XN + 3 * (size_t)WN, bo, out, nullptr);
}

// ---------------------------------------------------------------------------
// AdaIN stats (split-S, 16 segments, fp16 inputs, fp32 accum)
// ---------------------------------------------------------------------------
__global__ void k_stats()
{
    const int c   = blockIdx.x * 128 + threadIdx.x;
    const int b   = blockIdx.y;
    const int z   = blockIdx.z >> 4;
    const int seg = blockIdx.z & 15;
    const __half* src = z ? g_kp : g_qp;
    const __half* p = src + ((size_t)b * SS + seg * 64) * CC + c;

    float s0 = 0, s1 = 0, q0 = 0, q1 = 0;
#pragma unroll 4
    for (int s = 0; s < 64; s += 2) {
        float x0 = __half2float(p[(size_t)(s + 0) * CC]);
        float x1 = __half2float(p[(size_t)(s + 1) * CC]);
        s0 += x0; q0 = fmaf(x0, x0, q0);
        s1 += x1; q1 = fmaf(x1, x1, q1);
    }
    int idx = ((z * BB + b) * 16 + seg) * CC + c;
    g_psum[idx] = s0 + s1;
    g_psq [idx] = q0 + q1;
}

__global__ void k_finalize()
{
    int i = blockIdx.x * 256 + threadIdx.x;
    if (i >= 2 * BB * CC) return;
    int c  = i % CC;
    int b  = (i / CC) % BB;
    int z  = i / (CC * BB);
    int sb = (b < BB / 2) ? 0 : BB / 2;

    float sum = 0, sq = 0, sums = 0, sqs = 0;
#pragma unroll
    for (int seg = 0; seg < 16; seg++) {
        sum  += g_psum[((z * BB + b)  * 16 + seg) * CC + c];
        sq   += g_psq [((z * BB + b)  * 16 + seg) * CC + c];
        sums += g_psum[((z * BB + sb) * 16 + seg) * CC + c];
        sqs  += g_psq [((z * BB + sb) * 16 + seg) * CC + c];
    }
    float mean  = sum  * (1.0f / SS);
    float means = sums * (1.0f / SS);
    float sd  = sqrtf((sq  - sum  * mean ) * (1.0f / (SS - 1)) + EPSV);
    float sds = sqrtf((sqs - sums * means) * (1.0f / (SS - 1)) + EPSV);
    float scl = sds / sd;
    g_scl[i] = scl;
    g_shf[i] = means - mean * scl;
}

__global__ void k_apply()
{
    const int TOT4  = 2 * BB * SS * CC / 4;
    const int per_t = SS * CC / 4;
    int i4 = blockIdx.x * 256 + threadIdx.x;
    if (i4 >= TOT4) return;
    int zb = i4 / per_t;
    int r  = i4 % per_t;
    int c  = (r % (CC / 4)) * 4;
    const __half* pb = (zb < BB) ? g_qp : g_kp;
    __half*       hb = (zb < BB) ? g_qh : g_kh;
    int b = zb & 3;
    uint2 xin = ((const uint2*)(pb + (size_t)b * SS * CC))[r];
    __half2 h0 = *(__half2*)&xin.x;
    __half2 h1 = *(__half2*)&xin.y;
    float4 scl = *(const float4*)&g_scl[zb * CC + c];
    float4 shf = *(const float4*)&g_shf[zb * CC + c];
    uint2 t;
    t.x = pack_h2(fmaf(__low2float(h0),  scl.x, shf.x),
                  fmaf(__high2float(h0), scl.y, shf.y));
    t.y = pack_h2(fmaf(__low2float(h1),  scl.z, shf.z),
                  fmaf(__high2float(h1), scl.w, shf.w));
    ((uint2*)(hb + (size_t)b * SS * CC))[r] = t;
}

// ---------------------------------------------------------------------------
// Flash attention, fp16 m16n8k16 mma, persistent CTAs + atomic work queue.
// V is loaded ROW-MAJOR (like K) and transposed on the fly by
// ldmatrix.x4.trans -> no separate V-transpose pass or buffer.
// 3-stage cp.async ring, one barrier per chunk, P straight from the S
// accumulator, style dedup, max-free softmax (exp2; style bias = +1.0).
// ---------------------------------------------------------------------------
#define KS_OFF(s) ((s) * 18432)
#define VS_OFF(s) ((s) * 18432 + 9216)
#define ATT_SMEM  (3 * 18432)    // 55296 bytes
#define N_ITEMS 640

__global__ __launch_bounds__(256, 2) void k_attn_mma()
{
    extern __shared__ __align__(16) uint32_t sm[];
    __shared__ int s_item;
    char* smc = (char*)sm;

    const int tid  = threadIdx.x;
    const int warp = tid >> 5, lane = tid & 31;
    const int tg   = lane & 3, gid = lane >> 2;
    const int wq   = warp * 16;

    const uint32_t smb = smem_u32(sm);
    const int frow = tid >> 3, fcol = tid & 7;

    const int lr = lane & 7;
    const uint32_t aoff = ((wq + ((lane >> 3) & 1) * 8 + lr) * 72
                           + ((lane >> 4) & 1) * 8) * 2;
    const uint32_t kvoff = (((lane >> 4) * 8 + lr) * 72
                           + ((lane >> 3) & 1) * 8) * 2;
    // trans-LDSM lane offsets for V (rows = keys, cols = d)
    const uint32_t vtoff = (uint32_t)((((lane >> 3) & 1) * 8 + lr) * 144
                           + (lane >> 4) * 16);

    while (true) {
        if (tid == 0) s_item = atomicAdd(&g_ctr, 1);
        __syncthreads();
        const int item = s_item;
        if (item >= N_ITEMS) break;

        // decode: items 0..319 long (b=1,3), 320..639 short (b=0,2)
        int b, rem;
        if (item < 320) { b = 1 + 2 * (item / 160); rem = item % 160; }
        else            { int j = item - 320; b = 2 * (j / 160); rem = j % 160; }
        const int h  = rem / 8;
        const int q0 = (rem % 8) * 128;
        const int sbv = (b < BB / 2) ? 0 : BB / 2;
        const int nch = (b == sbv) ? 16 : 32;

        // ---- stage Q tile (128x64 fp16) through stage-0, grab frags ----
        {
            const __half* Qg = g_qh + (size_t)(b * SS + q0) * CC + h * DD;
#pragma unroll
            for (int i = 0; i < 4; i++) {
                int fid = tid + i * 256;
                int row = fid >> 3, c8 = fid & 7;
                *(uint4*)(smc + row * 144 + c8 * 16) =
                    *(const uint4*)(Qg + (size_t)row * CC + c8 * 8);
            }
        }
        __syncthreads();

        uint32_t qf[4][4];
#pragma unroll
        for (int ks = 0; ks < 4; ks++) LDSM_X4(qf[ks], smb + aoff + ks * 32);
        __syncthreads();   // Q reads done; stage 0 free for chunk 0

        float o[8][4];
#pragma unroll
        for (int n_ = 0; n_ < 8; n_++)
#pragma unroll
            for (int r = 0; r < 4; r++) o[n_][r] = 0.f;
        float l0r = 0.f, l1r = 0.f;

        const __half* Kbase0 = g_kh + (size_t)b * SS * CC + h * DD;
        const __half* Kbase1 = g_kh + (size_t)sbv * SS * CC + h * DD;
        const __half* Vbase0 = g_vh + (size_t)b * SS * CC + h * DD;
        const __half* Vbase1 = g_vh + (size_t)sbv * SS * CC + h * DD;

#define AISSUE(c, s) do { \
    const int _self = ((c) < 16); \
    const int _kr   = (_self ? (c) : (c) - 16) * 64; \
    const __half* _Kg = (_self ? Kbase0 : Kbase1) + (size_t)_kr * CC; \
    const __half* _Vg = (_self ? Vbase0 : Vbase1) + (size_t)_kr * CC; \
    uint32_t _kd = smb + KS_OFF(s) + frow * 144 + fcol * 16; \
    uint32_t _vd = smb + VS_OFF(s) + frow * 144 + fcol * 16; \
    _Pragma("unroll") \
    for (int _i = 0; _i < 2; _i++) { \
        int _row = frow + _i * 32; \
        CP_ASYNC16(_kd + _i * 32 * 144, _Kg + (size_t)_row * CC + fcol * 8); \
        CP_ASYNC16(_vd + _i * 32 * 144, _Vg + (size_t)_row * CC + fcol * 8); \
    } \
} while (0)

        AISSUE(0, 0); CP_COMMIT();
        AISSUE(1, 1); CP_COMMIT();

        int st = 0;
        for (int ch = 0; ch < nch; ch++) {
            const float b2 = (ch < 16) ? 0.f : 1.0f;   // log2(e)*ln2 == 1

            CP_WAIT1();
            __syncthreads();

            int is_ = st + 2; if (is_ >= 3) is_ -= 3;
            if (ch + 2 < nch) AISSUE(ch + 2, is_);
            CP_COMMIT();

            const uint32_t kbase = smb + KS_OFF(st) + kvoff;
            const uint32_t vbase = smb + VS_OFF(st) + vtoff;

            // ---- S = Q @ K^T (16 x 64 per warp), 4 k16 steps ----
            float sacc[8][4];
#pragma unroll
            for (int n_ = 0; n_ < 8; n_++)
#pragma unroll
                for (int r = 0; r < 4; r++) sacc[n_][r] = 0.f;

#pragma unroll
            for (int ks = 0; ks < 4; ks++) {
                uint32_t bf[4][4];
#pragma unroll
                for (int np = 0; np < 4; np++)
                    LDSM_X4(bf[np], kbase + np * 16 * 144 + ks * 32);
#pragma unroll
                for (int np = 0; np < 4; np++) {
                    mma_16816(sacc[2*np],     qf[ks], bf[np][0], bf[np][1]);
                    mma_16816(sacc[2*np + 1], qf[ks], bf[np][2], bf[np][3]);
                }
            }

            // ---- fused softmax + PV (V fragments via trans-LDSM) ----
#pragma unroll
            for (int j = 0; j < 4; j++) {
                float e0 = fexp2(fmaf(sacc[2*j][0], SC2, b2));
                float e1 = fexp2(fmaf(sacc[2*j][1], SC2, b2));
                float e2 = fexp2(fmaf(sacc[2*j][2], SC2, b2));
                float e3 = fexp2(fmaf(sacc[2*j][3], SC2, b2));
                float f0 = fexp2(fmaf(sacc[2*j+1][0], SC2, b2));
                float f1 = fexp2(fmaf(sacc[2*j+1][1], SC2, b2));
                float f2 = fexp2(fmaf(sacc[2*j+1][2], SC2, b2));
                float f3 = fexp2(fmaf(sacc[2*j+1][3], SC2, b2));
                l0r += (e0 + e1) + (f0 + f1);
                l1r += (e2 + e3) + (f2 + f3);
                uint32_t pf[4];
                pf[0] = pack_h2(e0, e1);
                pf[1] = pack_h2(e2, e3);
                pf[2] = pack_h2(f0, f1);
                pf[3] = pack_h2(f2, f3);

                uint32_t bf[4][4];
#pragma unroll
                for (int np = 0; np < 4; np++)
                    LDSM_X4T(bf[np], vbase + j * 16 * 144 + np * 32);
#pragma unroll
                for (int np = 0; np < 4; np++) {
                    mma_16816(o[2*np],     pf, bf[np][0], bf[np][1]);
                    mma_16816(o[2*np + 1], pf, bf[np][2], bf[np][3]);
                }
            }

            if (++st == 3) st = 0;
        }

        // ---- epilogue: quad-reduce row sums, normalize, store fp16 ----
        l0r += __shfl_xor_sync(0xffffffffu, l0r, 1);
        l0r += __shfl_xor_sync(0xffffffffu, l0r, 2);
        l1r += __shfl_xor_sync(0xffffffffu, l1r, 1);
        l1r += __shfl_xor_sync(0xffffffffu, l1r, 2);
        const float inv0 = 1.0f / l0r, inv1 = 1.0f / l1r;
        __half* Og = g_attnh + (size_t)(b * SS + q0 + wq) * CC + h * DD;
#pragma unroll
        for (int n_ = 0; n_ < 8; n_++) {
            int col = n_ * 8 + tg * 2;
            uint32_t lo = pack_h2(o[n_][0] * inv0, o[n_][1] * inv0);
            uint32_t hi = pack_h2(o[n_][2] * inv1, o[n_][3] * inv1);
            *(uint32_t*)(Og + (size_t)gid * CC + col)       = lo;
            *(uint32_t*)(Og + (size_t)(gid + 8) * CC + col) = hi;
        }
    }
}

// ---------------------------------------------------------------------------
extern "C" void kernel_launch(void* const* d_in, const int* in_sizes, int n_in,
                              void* d_out, int out_size)
{
    (void)in_sizes; (void)n_in; (void)out_size;
    const float* X  = (const float*)d_in[0];
    const float* Wq = (const float*)d_in[1];
    const float* Wk = (const float*)d_in[2];
    const float* Wv = (const float*)d_in[3];
    const float* Wo = (const float*)d_in[4];
    const float* bo = (const float*)d_in[5];
    float* out = (float*)d_out;

    cudaFuncSetAttribute(k_attn_mma, cudaFuncAttributeMaxDynamicSharedMemorySize,
                         ATT_SMEM);
    cudaFuncSetAttribute(k_qkv_mma, cudaFuncAttributeMaxDynamicSharedMemorySize,
                         GEMM_SMEM);
    cudaFuncSetAttribute(k_proj_mma, cudaFuncAttributeMaxDynamicSharedMemorySize,
                         GEMM_SMEM);

    k_cvt<<<(CVT_F4 + 255) / 256, 256>>>(X, Wq, Wk, Wv, Wo);
    k_qkv_mma<<<dim3(CC / 128, (BB * SS) / 128, 3), 256, GEMM_SMEM>>>();
    k_stats<<<dim3(CC / 128, BB, 32), 128>>>();
    k_finalize<<<(2 * BB * CC + 255) / 256, 256>>>();
    k_apply<<<(2 * BB * SS * CC / 4 + 255) / 256, 256>>>();
    k_attn_mma<<<304, 256, ATT_SMEM>>>();
    k_proj_mma<<<dim3(CC / 128, (BB * SS) / 128), 256, GEMM_SMEM>>>(bo, out);
}